// round 3
// baseline (speedup 1.0000x reference)
#include <cuda_runtime.h>
#include <cuda_bf16.h>
#include <math.h>

// Problem constants
#define NSER   1024
#define N3     3072          // 3 * NSER
#define BB     64            // batch
#define CC     64            // in channels == h_dim
#define MCOLS  4096          // B * C
#define HD2    128           // 2 * h_dim

// Scratch (allocation-free rule: __device__ globals)
__device__ float g_scratchG[(size_t)N3 * MCOLS];   // GEMM outputs (reused)
__device__ float g_scratchH[(size_t)N3 * MCOLS];   // depth-0 GLU output

// ---------------------------------------------------------------------------
// Tiled fp32 SGEMM: C[M,N] = A[M,K] @ B[K,N], all row-major.
// 128x128 block tile, BK=8, 256 threads, 8x8 per thread, double-buffered smem.
// M % 128 == 0, N % 128 == 0, K % 8 == 0 (guaranteed by problem shapes).
// ---------------------------------------------------------------------------
__global__ __launch_bounds__(256, 2)
void sgemm128(int M, int N, int K,
              const float* __restrict__ A,
              const float* __restrict__ B,
              float* __restrict__ C)
{
    constexpr int BM = 128, BN = 128, BK = 8;
    __shared__ float As[2][BK][BM + 4];   // transposed A tile, padded
    __shared__ float Bs[2][BK][BN];

    const int tid = threadIdx.x;
    const int tx  = tid & 15;     // 0..15 -> col micro tile
    const int ty  = tid >> 4;     // 0..15 -> row micro tile
    const int bm  = blockIdx.y * BM;
    const int bn  = blockIdx.x * BN;

    // A tile load mapping: 128 rows x 8 cols, one float4 per thread
    const int arow = tid >> 1;           // 0..127
    const int acol = (tid & 1) << 2;     // 0 or 4
    // B tile load mapping: 8 rows x 128 cols, one float4 per thread
    const int brow = tid >> 5;           // 0..7
    const int bcol = (tid & 31) << 2;    // 0..124

    const float* Aptr = A + (size_t)(bm + arow) * K + acol;
    const float* Bptr = B + (size_t)brow * N + bn + bcol;

    float acc[8][8];
    #pragma unroll
    for (int i = 0; i < 8; i++)
        #pragma unroll
        for (int j = 0; j < 8; j++) acc[i][j] = 0.0f;

    // prologue: load tile 0 into buffer 0
    float4 a4 = *(const float4*)Aptr;
    float4 b4 = *(const float4*)Bptr;
    As[0][acol + 0][arow] = a4.x;
    As[0][acol + 1][arow] = a4.y;
    As[0][acol + 2][arow] = a4.z;
    As[0][acol + 3][arow] = a4.w;
    *(float4*)&Bs[0][brow][bcol] = b4;
    __syncthreads();

    const int nt = K / BK;
    int buf = 0;
    for (int t = 0; t < nt; t++) {
        if (t + 1 < nt) {
            a4 = *(const float4*)(Aptr + (t + 1) * BK);
            b4 = *(const float4*)(Bptr + (size_t)(t + 1) * BK * N);
        }
        #pragma unroll
        for (int kk = 0; kk < BK; kk++) {
            float4 a0 = *(const float4*)&As[buf][kk][ty * 8];
            float4 a1 = *(const float4*)&As[buf][kk][ty * 8 + 4];
            float4 b0 = *(const float4*)&Bs[buf][kk][tx * 8];
            float4 b1 = *(const float4*)&Bs[buf][kk][tx * 8 + 4];
            float ar[8] = {a0.x, a0.y, a0.z, a0.w, a1.x, a1.y, a1.z, a1.w};
            float br[8] = {b0.x, b0.y, b0.z, b0.w, b1.x, b1.y, b1.z, b1.w};
            #pragma unroll
            for (int i = 0; i < 8; i++)
                #pragma unroll
                for (int j = 0; j < 8; j++)
                    acc[i][j] = fmaf(ar[i], br[j], acc[i][j]);
        }
        if (t + 1 < nt) {
            buf ^= 1;
            As[buf][acol + 0][arow] = a4.x;
            As[buf][acol + 1][arow] = a4.y;
            As[buf][acol + 2][arow] = a4.z;
            As[buf][acol + 3][arow] = a4.w;
            *(float4*)&Bs[buf][brow][bcol] = b4;
            __syncthreads();
        }
    }

    // epilogue
    #pragma unroll
    for (int i = 0; i < 8; i++) {
        float* cp = C + (size_t)(bm + ty * 8 + i) * N + bn + tx * 8;
        float4 v0 = make_float4(acc[i][0], acc[i][1], acc[i][2], acc[i][3]);
        float4 v1 = make_float4(acc[i][4], acc[i][5], acc[i][6], acc[i][7]);
        *(float4*)(cp)     = v0;
        *(float4*)(cp + 4) = v1;
    }
}

// ---------------------------------------------------------------------------
// Fused 1x1-conv + GLU (+ optional elementwise max against maxsrc).
// One thread per (v,b) pair. Input row g[64] in registers, W (128x64) in
// shared (warp-uniform broadcast reads).
//   y[o] = sum_c W[o,c]*g[c] + bias[o];  out[j] = y[j]*sigmoid(y[j+64])
// ---------------------------------------------------------------------------
__global__ __launch_bounds__(128)
void glu_max_kernel(const float* __restrict__ G,      // nPairs x 64
                    const float* __restrict__ W,      // 128 x 64
                    const float* __restrict__ bias,   // 128
                    const float* __restrict__ maxsrc, // nPairs x 64 or null
                    float* __restrict__ out)          // nPairs x 64
{
    __shared__ float Ws[HD2 * CC];   // 32 KB
    const int tid = threadIdx.x;

    #pragma unroll
    for (int i = tid; i < (HD2 * CC) / 4; i += 128)
        *(float4*)&Ws[i * 4] = *(const float4*)(W + i * 4);
    __syncthreads();

    const size_t p  = (size_t)blockIdx.x * 128 + tid;
    const float* gp = G + p * CC;

    float g[CC];
    #pragma unroll
    for (int c = 0; c < CC; c += 4) {
        float4 v = *(const float4*)(gp + c);
        g[c] = v.x; g[c + 1] = v.y; g[c + 2] = v.z; g[c + 3] = v.w;
    }

    float* op = out + p * CC;
    const float* mp = maxsrc ? (maxsrc + p * CC) : nullptr;

    #pragma unroll 2
    for (int j = 0; j < CC; j++) {
        float l = bias[j];
        float r = bias[j + CC];
        #pragma unroll
        for (int c = 0; c < CC; c++) {
            l = fmaf(Ws[j * CC + c],        g[c], l);
            r = fmaf(Ws[(j + CC) * CC + c], g[c], r);
        }
        float s = 1.0f / (1.0f + __expf(-r));
        float v = l * s;
        if (mp) v = fmaxf(v, mp[j]);
        op[j] = v;
    }
}

extern "C" void kernel_launch(void* const* d_in, const int* in_sizes, int n_in,
                              void* d_out, int out_size)
{
    const float* x  = (const float*)d_in[0];  // (3N, B, C) == (3072, 4096)
    const float* A  = (const float*)d_in[1];  // (3072, 3072)
    const float* W0 = (const float*)d_in[2];  // (128, 64)
    const float* b0 = (const float*)d_in[3];  // (128)
    const float* W1 = (const float*)d_in[4];  // (128, 64)
    const float* b1 = (const float*)d_in[5];  // (128)
    float* out = (float*)d_out;               // (1024, 64, 64)

    float *G = nullptr, *H = nullptr;
    cudaGetSymbolAddress((void**)&G, g_scratchG);
    cudaGetSymbolAddress((void**)&H, g_scratchH);

    // Depth 0: G0 = A @ X   (3072 x 4096)
    {
        dim3 grid(MCOLS / 128, N3 / 128);
        sgemm128<<<grid, 256>>>(N3, MCOLS, N3, A, x, G);
    }
    // Depth 0 GLU: H1[v,b,:] = glu(W0 @ G0[v,b,:] + b0)
    glu_max_kernel<<<(N3 * BB) / 128, 128>>>(G, W0, b0, nullptr, H);

    // Depth 1 (only cropped middle N rows needed): G1 = A[N:2N] @ H1  (1024 x 4096)
    {
        dim3 grid(MCOLS / 128, NSER / 128);
        sgemm128<<<grid, 256>>>(NSER, MCOLS, N3, A + (size_t)NSER * N3, H, G);
    }
    // Depth 1 GLU + max with cropped depth-0 output
    glu_max_kernel<<<(NSER * BB) / 128, 128>>>(G, W1, b1,
                                               H + (size_t)NSER * MCOLS, out);
}

// round 10
// speedup vs baseline: 1.7040x; 1.7040x over previous
#include <cuda_runtime.h>
#include <cuda_bf16.h>
#include <cstdint>

#define NSER 1024
#define N3   3072
#define MJ   4096     // B*C = 64*64 rows in transposed ("T") space
#define HD   64
#define HD2  128

// ---------------- scratch (__device__ globals; no allocs allowed) -----------
__device__ __nv_bfloat16 g_XT_hi[(size_t)MJ * N3];
__device__ __nv_bfloat16 g_XT_lo[(size_t)MJ * N3];
__device__ __nv_bfloat16 g_A_hi [(size_t)N3 * N3];
__device__ __nv_bfloat16 g_A_lo [(size_t)N3 * N3];
__device__ float         g_G    [(size_t)MJ * N3];   // GEMM output (reused)
__device__ __nv_bfloat16 g_H_hi [(size_t)MJ * N3];
__device__ __nv_bfloat16 g_H_lo [(size_t)MJ * N3];
__device__ float         g_Hmid [(size_t)MJ * NSER]; // fp32 depth-0 crop

// ---------------- PTX helpers (sm_80+ features only; no tcgen05) ------------
__device__ __forceinline__ uint32_t smem_u32(const void* p) {
    uint32_t a;
    asm("{ .reg .u64 t; cvta.to.shared.u64 t, %1; cvt.u32.u64 %0, t; }" : "=r"(a) : "l"(p));
    return a;
}
__device__ __forceinline__ void cpa16(uint32_t s, const void* g) {
    asm volatile("cp.async.cg.shared.global [%0], [%1], 16;" :: "r"(s), "l"(g) : "memory");
}
__device__ __forceinline__ void ldsm4(uint32_t& r0, uint32_t& r1, uint32_t& r2, uint32_t& r3,
                                      uint32_t a) {
    asm volatile("ldmatrix.sync.aligned.m8n8.x4.shared.b16 {%0,%1,%2,%3}, [%4];"
        : "=r"(r0), "=r"(r1), "=r"(r2), "=r"(r3) : "r"(a));
}
__device__ __forceinline__ void mma16816(float* d, const uint32_t* a, const uint32_t* b) {
    asm volatile("mma.sync.aligned.m16n8k16.row.col.f32.bf16.bf16.f32 "
        "{%0,%1,%2,%3}, {%4,%5,%6,%7}, {%8,%9}, {%0,%1,%2,%3};"
        : "+f"(d[0]), "+f"(d[1]), "+f"(d[2]), "+f"(d[3])
        : "r"(a[0]), "r"(a[1]), "r"(a[2]), "r"(a[3]), "r"(b[0]), "r"(b[1]));
}

// ---------------- warp-MMA GEMM: C[M,N] = sum_k P[m,k]*Q[n,k] ---------------
// P, Q bf16 K-major; 3 split segments (Ph*Qh + Ph*Ql + Pl*Qh) fused into one
// accumulation loop. CTA tile 128x128, BK=32, 256 threads, warp tile 64x32.
#define BM 128
#define BN 128
#define BK 32
#define LDT 40                 // smem row stride in halves (32 + 8 pad)
#define TILE_H (BM * LDT)      // halves per tile buffer

__global__ __launch_bounds__(256)
void hmma_gemm(const __nv_bfloat16* __restrict__ Ph,
               const __nv_bfloat16* __restrict__ Pl,
               const __nv_bfloat16* __restrict__ Qh,
               const __nv_bfloat16* __restrict__ Ql,
               float* __restrict__ C, int ldc, int K)
{
    __shared__ __nv_bfloat16 sA[2][TILE_H];
    __shared__ __nv_bfloat16 sB[2][TILE_H];

    const int tid  = threadIdx.x;
    const int lane = tid & 31;
    const int w    = tid >> 5;
    const int wr   = w >> 2;          // 0..1  (warp row)
    const int wc   = w & 3;           // 0..3  (warp col)
    const int bm   = blockIdx.y * BM;
    const int bn   = blockIdx.x * BN;
    const int ktiles = K / BK;
    const int T      = 3 * ktiles;

    const uint32_t sA0 = smem_u32(sA);
    const uint32_t sB0 = smem_u32(sB);

    // load mapping: each thread copies 2x16B for A and 2x16B for B per iter
    const int lrow  = tid >> 2;          // 0..63 (+64 on second rep)
    const int lcol8 = (tid & 3) * 8;     // halves

    auto issue = [&](int it, int buf) {
        const int kt  = it % ktiles;
        const int seg = it / ktiles;
        const __nv_bfloat16* P = (seg == 2) ? Pl : Ph;
        const __nv_bfloat16* Q = (seg == 1) ? Ql : Qh;
        const __nv_bfloat16* pg = P + (size_t)(bm + lrow) * K + kt * BK + lcol8;
        const __nv_bfloat16* qg = Q + (size_t)(bn + lrow) * K + kt * BK + lcol8;
        const uint32_t pa = sA0 + (uint32_t)buf * (TILE_H * 2) + (lrow * LDT + lcol8) * 2;
        const uint32_t qa = sB0 + (uint32_t)buf * (TILE_H * 2) + (lrow * LDT + lcol8) * 2;
        cpa16(pa, pg);
        cpa16(qa, qg);
        cpa16(pa + 64 * LDT * 2, pg + (size_t)64 * K);
        cpa16(qa + 64 * LDT * 2, qg + (size_t)64 * K);
        asm volatile("cp.async.commit_group;" ::: "memory");
    };

    float acc[4][4][4];
    #pragma unroll
    for (int i = 0; i < 4; i++)
        #pragma unroll
        for (int j = 0; j < 4; j++)
            #pragma unroll
            for (int e = 0; e < 4; e++) acc[i][j][e] = 0.0f;

    issue(0, 0);
    int buf = 0;
    for (int it = 0; it < T; it++) {
        asm volatile("cp.async.wait_group 0;" ::: "memory");
        __syncthreads();
        if (it + 1 < T) issue(it + 1, buf ^ 1);   // overlaps compute below

        const uint32_t aB = sA0 + (uint32_t)buf * (TILE_H * 2);
        const uint32_t bB = sB0 + (uint32_t)buf * (TILE_H * 2);
        #pragma unroll
        for (int ks = 0; ks < 2; ks++) {
            uint32_t af[4][4];
            uint32_t bfr[4][2];
            #pragma unroll
            for (int i = 0; i < 4; i++) {
                uint32_t ad = aB +
                    ((wr * 64 + i * 16 + (lane & 15)) * LDT + ks * 16 + (lane >> 4) * 8) * 2;
                ldsm4(af[i][0], af[i][1], af[i][2], af[i][3], ad);
            }
            #pragma unroll
            for (int jp = 0; jp < 2; jp++) {
                uint32_t r0, r1, r2, r3;
                uint32_t bd = bB +
                    ((wc * 32 + jp * 16 + (lane & 15)) * LDT + ks * 16 + (lane >> 4) * 8) * 2;
                ldsm4(r0, r1, r2, r3, bd);
                bfr[jp * 2][0]     = r0; bfr[jp * 2][1]     = r2;   // n0-7:  k0-7, k8-15
                bfr[jp * 2 + 1][0] = r1; bfr[jp * 2 + 1][1] = r3;   // n8-15
            }
            #pragma unroll
            for (int i = 0; i < 4; i++)
                #pragma unroll
                for (int j = 0; j < 4; j++)
                    mma16816(acc[i][j], af[i], bfr[j]);
        }
        buf ^= 1;
    }

    // epilogue: fp32 stores, mma d-fragment layout
    #pragma unroll
    for (int i = 0; i < 4; i++) {
        const int row = bm + wr * 64 + i * 16 + (lane >> 2);
        #pragma unroll
        for (int j = 0; j < 4; j++) {
            const int col = bn + wc * 32 + j * 8 + (lane & 3) * 2;
            *(float2*)&C[(size_t)row * ldc + col]       = make_float2(acc[i][j][0], acc[i][j][1]);
            *(float2*)&C[(size_t)(row + 8) * ldc + col] = make_float2(acc[i][j][2], acc[i][j][3]);
        }
    }
}

// ---------------- transpose + bf16 split of x -------------------------------
__global__ void transpose_split(const float* __restrict__ x,
                                __nv_bfloat16* __restrict__ xh,
                                __nv_bfloat16* __restrict__ xl)
{
    __shared__ float t[32][33];
    const int k0 = blockIdx.x * 32, j0 = blockIdx.y * 32;
    const int tx = threadIdx.x, ty = threadIdx.y;
    #pragma unroll
    for (int i = 0; i < 32; i += 8)
        t[ty + i][tx] = x[(size_t)(k0 + ty + i) * MJ + j0 + tx];
    __syncthreads();
    #pragma unroll
    for (int i = 0; i < 32; i += 8) {
        float v = t[tx][ty + i];
        __nv_bfloat16 h = __float2bfloat16(v);
        size_t o = (size_t)(j0 + ty + i) * N3 + k0 + tx;
        xh[o] = h;
        xl[o] = __float2bfloat16(v - __bfloat162float(h));
    }
}

__global__ void split_mat(const float* __restrict__ A,
                          __nv_bfloat16* __restrict__ hi,
                          __nv_bfloat16* __restrict__ lo, size_t n)
{
    size_t i = (size_t)blockIdx.x * blockDim.x + threadIdx.x;
    if (i < n) {
        float v = A[i];
        __nv_bfloat16 h = __float2bfloat16(v);
        hi[i] = h;
        lo[i] = __float2bfloat16(v - __bfloat162float(h));
    }
}

// ---------------- GLU in T-space --------------------------------------------
// depth 0: reads G0T [MJ][N3], writes H hi/lo [MJ][N3] and fp32 crop Hmid
__global__ __launch_bounds__(128)
void glu1(const float* __restrict__ G, const float* __restrict__ W,
          const float* __restrict__ bias,
          __nv_bfloat16* __restrict__ Hh, __nv_bfloat16* __restrict__ Hl,
          float* __restrict__ Hmid)
{
    __shared__ float Ws[HD2 * HD];
    const int tid = threadIdx.x;
    for (int i = tid; i < HD2 * HD / 4; i += 128)
        ((float4*)Ws)[i] = ((const float4*)W)[i];
    __syncthreads();
    const int b = blockIdx.y;
    const int v = blockIdx.x * 128 + tid;
    float g[HD];
    const float* gp = G + (size_t)b * HD * N3 + v;
    #pragma unroll
    for (int c = 0; c < HD; c++) g[c] = gp[(size_t)c * N3];
    #pragma unroll 1
    for (int j = 0; j < HD; j++) {
        float l = __ldg(bias + j), r = __ldg(bias + j + HD);
        #pragma unroll
        for (int c = 0; c < HD; c++) {
            l = fmaf(Ws[j * HD + c],        g[c], l);
            r = fmaf(Ws[(j + HD) * HD + c], g[c], r);
        }
        float val = l * (1.0f / (1.0f + __expf(-r)));
        size_t o = (size_t)(b * HD + j) * N3 + v;
        __nv_bfloat16 h = __float2bfloat16(val);
        Hh[o] = h;
        Hl[o] = __float2bfloat16(val - __bfloat162float(h));
        if ((unsigned)(v - NSER) < NSER)
            Hmid[(size_t)(b * HD + j) * NSER + (v - NSER)] = val;
    }
}

// depth 1: reads G1T [MJ][NSER], GLU, max with Hmid, transposed write to out
__global__ __launch_bounds__(128)
void glu2(const float* __restrict__ G, const float* __restrict__ W,
          const float* __restrict__ bias, const float* __restrict__ Hmid,
          float* __restrict__ out)
{
    extern __shared__ float sm2[];           // Ws[8192] + S[128*65]
    float* Ws = sm2;
    float* S  = sm2 + HD2 * HD;
    const int tid = threadIdx.x;
    for (int i = tid; i < HD2 * HD / 4; i += 128)
        ((float4*)Ws)[i] = ((const float4*)W)[i];
    __syncthreads();
    const int b = blockIdx.y;
    const int v = blockIdx.x * 128 + tid;
    float g[HD];
    const float* gp = G + (size_t)b * HD * NSER + v;
    #pragma unroll
    for (int c = 0; c < HD; c++) g[c] = gp[(size_t)c * NSER];
    #pragma unroll 1
    for (int j = 0; j < HD; j++) {
        float l = __ldg(bias + j), r = __ldg(bias + j + HD);
        #pragma unroll
        for (int c = 0; c < HD; c++) {
            l = fmaf(Ws[j * HD + c],        g[c], l);
            r = fmaf(Ws[(j + HD) * HD + c], g[c], r);
        }
        float val = l * (1.0f / (1.0f + __expf(-r)));
        float m = Hmid[(size_t)(b * HD + j) * NSER + v];
        S[tid * 65 + j] = fmaxf(val, m);
    }
    __syncthreads();
    const int v0 = blockIdx.x * 128;
    for (int i = tid; i < 128 * HD; i += 128) {
        int r = i >> 6, j = i & 63;
        out[(size_t)(v0 + r) * MJ + b * HD + j] = S[r * 65 + j];
    }
}

// ---------------- host -------------------------------------------------------
extern "C" void kernel_launch(void* const* d_in, const int* in_sizes, int n_in,
                              void* d_out, int out_size)
{
    const float* x  = (const float*)d_in[0];
    const float* A  = (const float*)d_in[1];
    const float* W0 = (const float*)d_in[2];
    const float* b0 = (const float*)d_in[3];
    const float* W1 = (const float*)d_in[4];
    const float* b1 = (const float*)d_in[5];
    float* out = (float*)d_out;

    void *XTh, *XTl, *Ah, *Al, *G, *Hh, *Hl, *Hmid;
    cudaGetSymbolAddress(&XTh, g_XT_hi);  cudaGetSymbolAddress(&XTl, g_XT_lo);
    cudaGetSymbolAddress(&Ah,  g_A_hi);   cudaGetSymbolAddress(&Al,  g_A_lo);
    cudaGetSymbolAddress(&G,   g_G);
    cudaGetSymbolAddress(&Hh,  g_H_hi);   cudaGetSymbolAddress(&Hl,  g_H_lo);
    cudaGetSymbolAddress(&Hmid, g_Hmid);

    cudaFuncSetAttribute(glu2, cudaFuncAttributeMaxDynamicSharedMemorySize,
                         (HD2 * HD + 128 * 65) * (int)sizeof(float));

    // 1) x (3N x 4096 row-major) -> XT (4096 x 3072) bf16 hi/lo
    transpose_split<<<dim3(N3 / 32, MJ / 32), dim3(32, 8)>>>(x,
        (__nv_bfloat16*)XTh, (__nv_bfloat16*)XTl);
    // 2) A -> bf16 hi/lo (rows of A are K-major already)
    {
        size_t n = (size_t)N3 * N3;
        split_mat<<<(unsigned)((n + 255) / 256), 256>>>(A,
            (__nv_bfloat16*)Ah, (__nv_bfloat16*)Al, n);
    }

    // 3) GEMM1: G0T[j,v] = sum_k XT[j,k]*A[v,k]   (4096 x 3072, K=3072)
    hmma_gemm<<<dim3(N3 / BN, MJ / BM), 256>>>(
        (const __nv_bfloat16*)XTh, (const __nv_bfloat16*)XTl,
        (const __nv_bfloat16*)Ah,  (const __nv_bfloat16*)Al,
        (float*)G, N3, N3);

    // 4) GLU depth 0 (T-space) -> H hi/lo + fp32 crop
    glu1<<<dim3(N3 / 128, 64), 128>>>((const float*)G, W0, b0,
        (__nv_bfloat16*)Hh, (__nv_bfloat16*)Hl, (float*)Hmid);

    // 5) GEMM2: G1T[j,v'] = sum_w H[j,w]*A[NSER+v',w]   (4096 x 1024)
    hmma_gemm<<<dim3(NSER / BN, MJ / BM), 256>>>(
        (const __nv_bfloat16*)Hh, (const __nv_bfloat16*)Hl,
        (const __nv_bfloat16*)Ah + (size_t)NSER * N3,
        (const __nv_bfloat16*)Al + (size_t)NSER * N3,
        (float*)G, NSER, N3);

    // 6) GLU depth 1 + max + transposed write to out (N, B, h)
    glu2<<<dim3(NSER / 128, 64), 128,
           (HD2 * HD + 128 * 65) * (int)sizeof(float)>>>(
        (const float*)G, W1, b1, (const float*)Hmid, out);
}

// round 12
// speedup vs baseline: 1.7948x; 1.0533x over previous
#include <cuda_runtime.h>
#include <cuda_bf16.h>
#include <cstdint>

#define NSER 1024
#define N3   3072
#define MJ   4096     // B*C = 64*64 rows in transposed ("T") space
#define HD   64
#define HD2  128

// ---------------- scratch (__device__ globals; no allocs allowed) -----------
__device__ __nv_bfloat16 g_XT_hi[(size_t)MJ * N3];
__device__ __nv_bfloat16 g_XT_lo[(size_t)MJ * N3];
__device__ __nv_bfloat16 g_A_hi [(size_t)N3 * N3];
__device__ __nv_bfloat16 g_A_lo [(size_t)N3 * N3];
__device__ float         g_G    [(size_t)MJ * N3];   // GEMM output (reused)
__device__ __nv_bfloat16 g_H_hi [(size_t)MJ * N3];
__device__ __nv_bfloat16 g_H_lo [(size_t)MJ * N3];
__device__ float         g_Hmid [(size_t)MJ * NSER]; // fp32 depth-0 crop

// ---------------- PTX helpers (sm_80+ features only) ------------------------
__device__ __forceinline__ uint32_t smem_u32(const void* p) {
    uint32_t a;
    asm("{ .reg .u64 t; cvta.to.shared.u64 t, %1; cvt.u32.u64 %0, t; }" : "=r"(a) : "l"(p));
    return a;
}
__device__ __forceinline__ void cpa16(uint32_t s, const void* g) {
    asm volatile("cp.async.cg.shared.global [%0], [%1], 16;" :: "r"(s), "l"(g) : "memory");
}
__device__ __forceinline__ void ldsm4(uint32_t& r0, uint32_t& r1, uint32_t& r2, uint32_t& r3,
                                      uint32_t a) {
    asm volatile("ldmatrix.sync.aligned.m8n8.x4.shared.b16 {%0,%1,%2,%3}, [%4];"
        : "=r"(r0), "=r"(r1), "=r"(r2), "=r"(r3) : "r"(a));
}
__device__ __forceinline__ void mma16816(float* d, const uint32_t* a, const uint32_t* b) {
    asm volatile("mma.sync.aligned.m16n8k16.row.col.f32.bf16.bf16.f32 "
        "{%0,%1,%2,%3}, {%4,%5,%6,%7}, {%8,%9}, {%0,%1,%2,%3};"
        : "+f"(d[0]), "+f"(d[1]), "+f"(d[2]), "+f"(d[3])
        : "r"(a[0]), "r"(a[1]), "r"(a[2]), "r"(a[3]), "r"(b[0]), "r"(b[1]));
}

// ---------------- warp-MMA GEMM: C[M,N] = sum_k P[m,k]*Q[n,k] ---------------
// bf16x3 split (Ph*Qh + Ph*Ql + Pl*Qh) fused: 4 tiles loaded per K-tile, 3
// MMA sets against them. CTA 128x128, BK=32, 256 thr, warp tile 64x32,
// double-buffered cp.async (dynamic smem 80KB), 2 CTAs/SM.
#define BM 128
#define BN 128
#define BK 32
#define LDT 40                     // smem row stride in halves (32 + 8 pad)
#define TILE_H (BM * LDT)          // 5120 halves per tile
#define STAGE_H (4 * TILE_H)       // 20480 halves per stage (Ah,Al,Bh,Bl)
#define SMEM_GEMM (2 * STAGE_H * 2)  // bytes = 81920

__global__ __launch_bounds__(256, 2)
void hmma_gemm(const __nv_bfloat16* __restrict__ Ph,
               const __nv_bfloat16* __restrict__ Pl,
               const __nv_bfloat16* __restrict__ Qh,
               const __nv_bfloat16* __restrict__ Ql,
               float* __restrict__ C, int ldc, int K)
{
    extern __shared__ __nv_bfloat16 sm[];

    const int tid  = threadIdx.x;
    const int lane = tid & 31;
    const int w    = tid >> 5;
    const int wr   = w >> 2;          // 0..1  (warp row)
    const int wc   = w & 3;           // 0..3  (warp col)
    const int bm   = blockIdx.y * BM;
    const int bn   = blockIdx.x * BN;
    const int ktiles = K / BK;

    const uint32_t s0 = smem_u32(sm);

    // load mapping: 2 threads per row; each thread 2x16B per tile, 4 tiles
    const int lrow  = tid >> 1;          // 0..127
    const int lcolh = (tid & 1) * 16;    // halves (0 or 16)

    auto issue = [&](int kt, int buf) {
        const size_t pOff = (size_t)(bm + lrow) * K + kt * BK + lcolh;
        const size_t qOff = (size_t)(bn + lrow) * K + kt * BK + lcolh;
        const uint32_t sb = s0 + (uint32_t)buf * (STAGE_H * 2) + (lrow * LDT + lcolh) * 2;
        cpa16(sb,                    Ph + pOff);
        cpa16(sb + 16,               Ph + pOff + 8);
        cpa16(sb + TILE_H * 2,       Pl + pOff);
        cpa16(sb + TILE_H * 2 + 16,  Pl + pOff + 8);
        cpa16(sb + TILE_H * 4,       Qh + qOff);
        cpa16(sb + TILE_H * 4 + 16,  Qh + qOff + 8);
        cpa16(sb + TILE_H * 6,       Ql + qOff);
        cpa16(sb + TILE_H * 6 + 16,  Ql + qOff + 8);
        asm volatile("cp.async.commit_group;" ::: "memory");
    };

    float acc[4][4][4];
    #pragma unroll
    for (int i = 0; i < 4; i++)
        #pragma unroll
        for (int j = 0; j < 4; j++)
            #pragma unroll
            for (int e = 0; e < 4; e++) acc[i][j][e] = 0.0f;

    // per-warp ldmatrix base offsets (within a tile, in halves)
    const int aRow = wr * 64 + (lane & 15);
    const int bRow = wc * 32 + (lane & 15);
    const int kHi  = (lane >> 4) * 8;

    issue(0, 0);
    int buf = 0;
    for (int it = 0; it < ktiles; it++) {
        asm volatile("cp.async.wait_group 0;" ::: "memory");
        __syncthreads();
        if (it + 1 < ktiles) issue(it + 1, buf ^ 1);

        const uint32_t stg = s0 + (uint32_t)buf * (STAGE_H * 2);
        #pragma unroll
        for (int ks = 0; ks < 2; ks++) {
            const int kc = ks * 16 + kHi;
            // --- hi A frags ---
            uint32_t ah[4][4];
            #pragma unroll
            for (int i = 0; i < 4; i++)
                ldsm4(ah[i][0], ah[i][1], ah[i][2], ah[i][3],
                      stg + ((aRow + i * 16) * LDT + kc) * 2);
            // --- hi B frags ---
            uint32_t bh[4][2];
            #pragma unroll
            for (int jp = 0; jp < 2; jp++) {
                uint32_t r0, r1, r2, r3;
                ldsm4(r0, r1, r2, r3,
                      stg + TILE_H * 4 + ((bRow + jp * 16) * LDT + kc) * 2);
                bh[jp * 2][0] = r0; bh[jp * 2][1] = r2;
                bh[jp * 2 + 1][0] = r1; bh[jp * 2 + 1][1] = r3;
            }
            #pragma unroll
            for (int i = 0; i < 4; i++)
                #pragma unroll
                for (int j = 0; j < 4; j++)
                    mma16816(acc[i][j], ah[i], bh[j]);
            // --- lo B frags: Ah * Ql ---
            {
                uint32_t bl[4][2];
                #pragma unroll
                for (int jp = 0; jp < 2; jp++) {
                    uint32_t r0, r1, r2, r3;
                    ldsm4(r0, r1, r2, r3,
                          stg + TILE_H * 6 + ((bRow + jp * 16) * LDT + kc) * 2);
                    bl[jp * 2][0] = r0; bl[jp * 2][1] = r2;
                    bl[jp * 2 + 1][0] = r1; bl[jp * 2 + 1][1] = r3;
                }
                #pragma unroll
                for (int i = 0; i < 4; i++)
                    #pragma unroll
                    for (int j = 0; j < 4; j++)
                        mma16816(acc[i][j], ah[i], bl[j]);
            }
            // --- lo A frags: Al * Qh ---
            {
                #pragma unroll
                for (int i = 0; i < 4; i++) {
                    uint32_t al[4];
                    ldsm4(al[0], al[1], al[2], al[3],
                          stg + TILE_H * 2 + ((aRow + i * 16) * LDT + kc) * 2);
                    #pragma unroll
                    for (int j = 0; j < 4; j++)
                        mma16816(acc[i][j], al, bh[j]);
                }
            }
        }
        buf ^= 1;
    }

    // epilogue
    #pragma unroll
    for (int i = 0; i < 4; i++) {
        const int row = bm + wr * 64 + i * 16 + (lane >> 2);
        #pragma unroll
        for (int j = 0; j < 4; j++) {
            const int col = bn + wc * 32 + j * 8 + (lane & 3) * 2;
            *(float2*)&C[(size_t)row * ldc + col]       = make_float2(acc[i][j][0], acc[i][j][1]);
            *(float2*)&C[(size_t)(row + 8) * ldc + col] = make_float2(acc[i][j][2], acc[i][j][3]);
        }
    }
}

// ---------------- transpose + bf16 split of x -------------------------------
__global__ void transpose_split(const float* __restrict__ x,
                                __nv_bfloat16* __restrict__ xh,
                                __nv_bfloat16* __restrict__ xl)
{
    __shared__ float t[32][33];
    const int k0 = blockIdx.x * 32, j0 = blockIdx.y * 32;
    const int tx = threadIdx.x, ty = threadIdx.y;
    #pragma unroll
    for (int i = 0; i < 32; i += 8)
        t[ty + i][tx] = x[(size_t)(k0 + ty + i) * MJ + j0 + tx];
    __syncthreads();
    #pragma unroll
    for (int i = 0; i < 32; i += 8) {
        float v = t[tx][ty + i];
        __nv_bfloat16 h = __float2bfloat16(v);
        size_t o = (size_t)(j0 + ty + i) * N3 + k0 + tx;
        xh[o] = h;
        xl[o] = __float2bfloat16(v - __bfloat162float(h));
    }
}

__global__ void split_mat(const float* __restrict__ A,
                          __nv_bfloat16* __restrict__ hi,
                          __nv_bfloat16* __restrict__ lo, size_t n)
{
    size_t i = (size_t)blockIdx.x * blockDim.x + threadIdx.x;
    if (i < n) {
        float v = A[i];
        __nv_bfloat16 h = __float2bfloat16(v);
        hi[i] = h;
        lo[i] = __float2bfloat16(v - __bfloat162float(h));
    }
}

// ---------------- GLU in T-space (float4-vectorized weight reads) -----------
__global__ __launch_bounds__(128)
void glu1(const float* __restrict__ G, const float* __restrict__ W,
          const float* __restrict__ bias,
          __nv_bfloat16* __restrict__ Hh, __nv_bfloat16* __restrict__ Hl,
          float* __restrict__ Hmid)
{
    __shared__ float Ws[HD2 * HD];
    const int tid = threadIdx.x;
    for (int i = tid; i < HD2 * HD / 4; i += 128)
        ((float4*)Ws)[i] = ((const float4*)W)[i];
    __syncthreads();
    const float4* W4 = (const float4*)Ws;
    const int b = blockIdx.y;
    const int v = blockIdx.x * 128 + tid;
    float g[HD];
    const float* gp = G + (size_t)b * HD * N3 + v;
    #pragma unroll
    for (int c = 0; c < HD; c++) g[c] = gp[(size_t)c * N3];
    #pragma unroll 1
    for (int j = 0; j < HD; j++) {
        float l = __ldg(bias + j), r = __ldg(bias + j + HD);
        #pragma unroll
        for (int c4 = 0; c4 < HD / 4; c4++) {
            float4 wl = W4[j * (HD / 4) + c4];
            float4 wr = W4[(j + HD) * (HD / 4) + c4];
            l = fmaf(wl.x, g[c4 * 4 + 0], l);
            l = fmaf(wl.y, g[c4 * 4 + 1], l);
            l = fmaf(wl.z, g[c4 * 4 + 2], l);
            l = fmaf(wl.w, g[c4 * 4 + 3], l);
            r = fmaf(wr.x, g[c4 * 4 + 0], r);
            r = fmaf(wr.y, g[c4 * 4 + 1], r);
            r = fmaf(wr.z, g[c4 * 4 + 2], r);
            r = fmaf(wr.w, g[c4 * 4 + 3], r);
        }
        float val = l * (1.0f / (1.0f + __expf(-r)));
        size_t o = (size_t)(b * HD + j) * N3 + v;
        __nv_bfloat16 h = __float2bfloat16(val);
        Hh[o] = h;
        Hl[o] = __float2bfloat16(val - __bfloat162float(h));
        if ((unsigned)(v - NSER) < NSER)
            Hmid[(size_t)(b * HD + j) * NSER + (v - NSER)] = val;
    }
}

__global__ __launch_bounds__(128)
void glu2(const float* __restrict__ G, const float* __restrict__ W,
          const float* __restrict__ bias, const float* __restrict__ Hmid,
          float* __restrict__ out)
{
    extern __shared__ float sm2[];           // Ws[8192] + S[128*65]
    float* Ws = sm2;
    float* S  = sm2 + HD2 * HD;
    const int tid = threadIdx.x;
    for (int i = tid; i < HD2 * HD / 4; i += 128)
        ((float4*)Ws)[i] = ((const float4*)W)[i];
    __syncthreads();
    const float4* W4 = (const float4*)Ws;
    const int b = blockIdx.y;
    const int v = blockIdx.x * 128 + tid;
    float g[HD];
    const float* gp = G + (size_t)b * HD * NSER + v;
    #pragma unroll
    for (int c = 0; c < HD; c++) g[c] = gp[(size_t)c * NSER];
    #pragma unroll 1
    for (int j = 0; j < HD; j++) {
        float l = __ldg(bias + j), r = __ldg(bias + j + HD);
        #pragma unroll
        for (int c4 = 0; c4 < HD / 4; c4++) {
            float4 wl = W4[j * (HD / 4) + c4];
            float4 wr = W4[(j + HD) * (HD / 4) + c4];
            l = fmaf(wl.x, g[c4 * 4 + 0], l);
            l = fmaf(wl.y, g[c4 * 4 + 1], l);
            l = fmaf(wl.z, g[c4 * 4 + 2], l);
            l = fmaf(wl.w, g[c4 * 4 + 3], l);
            r = fmaf(wr.x, g[c4 * 4 + 0], r);
            r = fmaf(wr.y, g[c4 * 4 + 1], r);
            r = fmaf(wr.z, g[c4 * 4 + 2], r);
            r = fmaf(wr.w, g[c4 * 4 + 3], r);
        }
        float val = l * (1.0f / (1.0f + __expf(-r)));
        float m = Hmid[(size_t)(b * HD + j) * NSER + v];
        S[tid * 65 + j] = fmaxf(val, m);
    }
    __syncthreads();
    const int v0 = blockIdx.x * 128;
    for (int i = tid; i < 128 * HD; i += 128) {
        int r = i >> 6, j = i & 63;
        out[(size_t)(v0 + r) * MJ + b * HD + j] = S[r * 65 + j];
    }
}

// ---------------- host -------------------------------------------------------
extern "C" void kernel_launch(void* const* d_in, const int* in_sizes, int n_in,
                              void* d_out, int out_size)
{
    const float* x  = (const float*)d_in[0];
    const float* A  = (const float*)d_in[1];
    const float* W0 = (const float*)d_in[2];
    const float* b0 = (const float*)d_in[3];
    const float* W1 = (const float*)d_in[4];
    const float* b1 = (const float*)d_in[5];
    float* out = (float*)d_out;

    void *XTh, *XTl, *Ah, *Al, *G, *Hh, *Hl, *Hmid;
    cudaGetSymbolAddress(&XTh, g_XT_hi);  cudaGetSymbolAddress(&XTl, g_XT_lo);
    cudaGetSymbolAddress(&Ah,  g_A_hi);   cudaGetSymbolAddress(&Al,  g_A_lo);
    cudaGetSymbolAddress(&G,   g_G);
    cudaGetSymbolAddress(&Hh,  g_H_hi);   cudaGetSymbolAddress(&Hl,  g_H_lo);
    cudaGetSymbolAddress(&Hmid, g_Hmid);

    cudaFuncSetAttribute(hmma_gemm, cudaFuncAttributeMaxDynamicSharedMemorySize, SMEM_GEMM);
    cudaFuncSetAttribute(glu2, cudaFuncAttributeMaxDynamicSharedMemorySize,
                         (HD2 * HD + 128 * 65) * (int)sizeof(float));

    // 1) x (3N x 4096 row-major) -> XT (4096 x 3072) bf16 hi/lo
    transpose_split<<<dim3(N3 / 32, MJ / 32), dim3(32, 8)>>>(x,
        (__nv_bfloat16*)XTh, (__nv_bfloat16*)XTl);
    // 2) A -> bf16 hi/lo (rows of A are K-major already)
    {
        size_t n = (size_t)N3 * N3;
        split_mat<<<(unsigned)((n + 255) / 256), 256>>>(A,
            (__nv_bfloat16*)Ah, (__nv_bfloat16*)Al, n);
    }

    // 3) GEMM1: G0T[j,v] = sum_k XT[j,k]*A[v,k]   (4096 x 3072, K=3072)
    hmma_gemm<<<dim3(N3 / BN, MJ / BM), 256, SMEM_GEMM>>>(
        (const __nv_bfloat16*)XTh, (const __nv_bfloat16*)XTl,
        (const __nv_bfloat16*)Ah,  (const __nv_bfloat16*)Al,
        (float*)G, N3, N3);

    // 4) GLU depth 0 (T-space) -> H hi/lo + fp32 crop
    glu1<<<dim3(N3 / 128, 64), 128>>>((const float*)G, W0, b0,
        (__nv_bfloat16*)Hh, (__nv_bfloat16*)Hl, (float*)Hmid);

    // 5) GEMM2: G1T[j,v'] = sum_w H[j,w]*A[NSER+v',w]   (4096 x 1024)
    hmma_gemm<<<dim3(NSER / BN, MJ / BM), 256, SMEM_GEMM>>>(
        (const __nv_bfloat16*)Hh, (const __nv_bfloat16*)Hl,
        (const __nv_bfloat16*)Ah + (size_t)NSER * N3,
        (const __nv_bfloat16*)Al + (size_t)NSER * N3,
        (float*)G, NSER, N3);

    // 6) GLU depth 1 + max + transposed write to out (N, B, h)
    glu2<<<dim3(NSER / 128, 64), 128,
           (HD2 * HD + 128 * 65) * (int)sizeof(float)>>>(
        (const float*)G, W1, b1, (const float*)Hmid, out);
}

// round 14
// speedup vs baseline: 2.4568x; 1.3688x over previous
#include <cuda_runtime.h>
#include <cuda_fp16.h>
#include <cstdint>

#define NSER 1024
#define N3   3072
#define MJ   4096     // B*C = 64*64 rows in transposed ("T") space
#define HD   64
#define HD2  128
#define ASCALE    64.0f
#define INV_ASCALE 0.015625f

// ---------------- scratch (__device__ globals; no allocs allowed) -----------
__device__ __half g_XT  [(size_t)MJ * N3];           // fp16(x^T)
__device__ __half g_A_hi[(size_t)N3 * N3];           // fp16(64*A)
__device__ __half g_A_lo[(size_t)N3 * N3];           // fp16(64*A - hi)
__device__ float  g_G   [(size_t)MJ * N3];           // GEMM output (reused), scaled x64
__device__ __half g_H   [(size_t)MJ * N3];           // fp16 depth-0 GLU output
__device__ float  g_Hmid[(size_t)MJ * NSER];         // fp32 depth-0 crop (unscaled)

// ---------------- PTX helpers (sm_80+ features only) ------------------------
__device__ __forceinline__ uint32_t smem_u32(const void* p) {
    uint32_t a;
    asm("{ .reg .u64 t; cvta.to.shared.u64 t, %1; cvt.u32.u64 %0, t; }" : "=r"(a) : "l"(p));
    return a;
}
__device__ __forceinline__ void cpa16(uint32_t s, const void* g) {
    asm volatile("cp.async.cg.shared.global [%0], [%1], 16;" :: "r"(s), "l"(g) : "memory");
}
__device__ __forceinline__ void ldsm4(uint32_t& r0, uint32_t& r1, uint32_t& r2, uint32_t& r3,
                                      uint32_t a) {
    asm volatile("ldmatrix.sync.aligned.m8n8.x4.shared.b16 {%0,%1,%2,%3}, [%4];"
        : "=r"(r0), "=r"(r1), "=r"(r2), "=r"(r3) : "r"(a));
}
__device__ __forceinline__ void mma16816(float* d, const uint32_t* a, const uint32_t* b) {
    asm volatile("mma.sync.aligned.m16n8k16.row.col.f32.f16.f16.f32 "
        "{%0,%1,%2,%3}, {%4,%5,%6,%7}, {%8,%9}, {%0,%1,%2,%3};"
        : "+f"(d[0]), "+f"(d[1]), "+f"(d[2]), "+f"(d[3])
        : "r"(a[0]), "r"(a[1]), "r"(a[2]), "r"(a[3]), "r"(b[0]), "r"(b[1]));
}

// ---------------- warp-MMA GEMM: C[M,N] = sum_k P[m,k]*Q[n,k] ---------------
// fp16x2: Q split hi/lo, P hi only. 2 MMA sets (P*Qh + P*Ql) per K-tile.
// CTA 128x128, BK=32, 256 thr, warp tile 64x32, double-buffered cp.async.
#define BM 128
#define BN 128
#define BK 32
#define LDT 40                         // smem row stride in halves (32 + 8 pad)
#define TILE_H (BM * LDT)              // 5120 halves per tile
#define STAGE_H (3 * TILE_H)           // P, Qh, Ql
#define SMEM_GEMM (2 * STAGE_H * 2)    // bytes = 61440

__global__ __launch_bounds__(256, 2)
void hmma_gemm(const __half* __restrict__ P,
               const __half* __restrict__ Qh,
               const __half* __restrict__ Ql,
               float* __restrict__ C, int ldc, int K)
{
    extern __shared__ __half sm[];

    const int tid  = threadIdx.x;
    const int lane = tid & 31;
    const int w    = tid >> 5;
    const int wr   = w >> 2;          // 0..1  (warp row)
    const int wc   = w & 3;           // 0..3  (warp col)
    const int bm   = blockIdx.y * BM;
    const int bn   = blockIdx.x * BN;
    const int ktiles = K / BK;

    const uint32_t s0 = smem_u32(sm);

    // load mapping: 2 threads per row; each thread 2x16B per tile, 3 tiles
    const int lrow  = tid >> 1;          // 0..127
    const int lcolh = (tid & 1) * 16;    // halves (0 or 16)

    auto issue = [&](int kt, int buf) {
        const size_t pOff = (size_t)(bm + lrow) * K + kt * BK + lcolh;
        const size_t qOff = (size_t)(bn + lrow) * K + kt * BK + lcolh;
        const uint32_t sb = s0 + (uint32_t)buf * (STAGE_H * 2) + (lrow * LDT + lcolh) * 2;
        cpa16(sb,                    P  + pOff);
        cpa16(sb + 16,               P  + pOff + 8);
        cpa16(sb + TILE_H * 2,       Qh + qOff);
        cpa16(sb + TILE_H * 2 + 16,  Qh + qOff + 8);
        cpa16(sb + TILE_H * 4,       Ql + qOff);
        cpa16(sb + TILE_H * 4 + 16,  Ql + qOff + 8);
        asm volatile("cp.async.commit_group;" ::: "memory");
    };

    float acc[4][4][4];
    #pragma unroll
    for (int i = 0; i < 4; i++)
        #pragma unroll
        for (int j = 0; j < 4; j++)
            #pragma unroll
            for (int e = 0; e < 4; e++) acc[i][j][e] = 0.0f;

    // per-warp ldmatrix base offsets (within a tile, in halves)
    const int aRow = wr * 64 + (lane & 15);
    const int bRow = wc * 32 + (lane & 15);
    const int kHi  = (lane >> 4) * 8;

    issue(0, 0);
    int buf = 0;
    for (int it = 0; it < ktiles; it++) {
        asm volatile("cp.async.wait_group 0;" ::: "memory");
        __syncthreads();
        if (it + 1 < ktiles) issue(it + 1, buf ^ 1);

        const uint32_t stg = s0 + (uint32_t)buf * (STAGE_H * 2);
        #pragma unroll
        for (int ks = 0; ks < 2; ks++) {
            const int kc = ks * 16 + kHi;
            // --- P frags ---
            uint32_t ah[4][4];
            #pragma unroll
            for (int i = 0; i < 4; i++)
                ldsm4(ah[i][0], ah[i][1], ah[i][2], ah[i][3],
                      stg + ((aRow + i * 16) * LDT + kc) * 2);
            // --- Qh frags + MMA set 1 ---
            uint32_t bh[4][2];
            #pragma unroll
            for (int jp = 0; jp < 2; jp++) {
                uint32_t r0, r1, r2, r3;
                ldsm4(r0, r1, r2, r3,
                      stg + TILE_H * 2 + ((bRow + jp * 16) * LDT + kc) * 2);
                bh[jp * 2][0] = r0; bh[jp * 2][1] = r2;
                bh[jp * 2 + 1][0] = r1; bh[jp * 2 + 1][1] = r3;
            }
            #pragma unroll
            for (int i = 0; i < 4; i++)
                #pragma unroll
                for (int j = 0; j < 4; j++)
                    mma16816(acc[i][j], ah[i], bh[j]);
            // --- Ql frags + MMA set 2 ---
            {
                uint32_t bl[4][2];
                #pragma unroll
                for (int jp = 0; jp < 2; jp++) {
                    uint32_t r0, r1, r2, r3;
                    ldsm4(r0, r1, r2, r3,
                          stg + TILE_H * 4 + ((bRow + jp * 16) * LDT + kc) * 2);
                    bl[jp * 2][0] = r0; bl[jp * 2][1] = r2;
                    bl[jp * 2 + 1][0] = r1; bl[jp * 2 + 1][1] = r3;
                }
                #pragma unroll
                for (int i = 0; i < 4; i++)
                    #pragma unroll
                    for (int j = 0; j < 4; j++)
                        mma16816(acc[i][j], ah[i], bl[j]);
            }
        }
        buf ^= 1;
    }

    // epilogue
    #pragma unroll
    for (int i = 0; i < 4; i++) {
        const int row = bm + wr * 64 + i * 16 + (lane >> 2);
        #pragma unroll
        for (int j = 0; j < 4; j++) {
            const int col = bn + wc * 32 + j * 8 + (lane & 3) * 2;
            *(float2*)&C[(size_t)row * ldc + col]       = make_float2(acc[i][j][0], acc[i][j][1]);
            *(float2*)&C[(size_t)(row + 8) * ldc + col] = make_float2(acc[i][j][2], acc[i][j][3]);
        }
    }
}

// ---------------- transpose of x to fp16 ------------------------------------
__global__ void transpose_h(const float* __restrict__ x,
                            __half* __restrict__ xh)
{
    __shared__ float t[32][33];
    const int k0 = blockIdx.x * 32, j0 = blockIdx.y * 32;
    const int tx = threadIdx.x, ty = threadIdx.y;
    #pragma unroll
    for (int i = 0; i < 32; i += 8)
        t[ty + i][tx] = x[(size_t)(k0 + ty + i) * MJ + j0 + tx];
    __syncthreads();
    #pragma unroll
    for (int i = 0; i < 32; i += 8)
        xh[(size_t)(j0 + ty + i) * N3 + k0 + tx] = __float2half(t[tx][ty + i]);
}

// scale by 64 and split into fp16 hi/lo
__global__ void split_mat(const float* __restrict__ A,
                          __half* __restrict__ hi,
                          __half* __restrict__ lo, size_t n)
{
    size_t i = (size_t)blockIdx.x * blockDim.x + threadIdx.x;
    if (i < n) {
        float v = A[i] * ASCALE;
        __half h = __float2half(v);
        hi[i] = h;
        lo[i] = __float2half(v - __half2float(h));
    }
}

// ---------------- GLU in T-space --------------------------------------------
// depth 0: reads scaled G0T [MJ][N3], writes fp16 H [MJ][N3] and fp32 crop
__global__ __launch_bounds__(128)
void glu1(const float* __restrict__ G, const float* __restrict__ W,
          const float* __restrict__ bias,
          __half* __restrict__ Hh, float* __restrict__ Hmid)
{
    __shared__ float Ws[HD2 * HD];
    const int tid = threadIdx.x;
    for (int i = tid; i < HD2 * HD / 4; i += 128)
        ((float4*)Ws)[i] = ((const float4*)W)[i];
    __syncthreads();
    const float4* W4 = (const float4*)Ws;
    const int b = blockIdx.y;
    const int v = blockIdx.x * 128 + tid;
    float g[HD];
    const float* gp = G + (size_t)b * HD * N3 + v;
    #pragma unroll
    for (int c = 0; c < HD; c++) g[c] = gp[(size_t)c * N3] * INV_ASCALE;
    #pragma unroll 1
    for (int j = 0; j < HD; j++) {
        float l = __ldg(bias + j), r = __ldg(bias + j + HD);
        #pragma unroll
        for (int c4 = 0; c4 < HD / 4; c4++) {
            float4 wl = W4[j * (HD / 4) + c4];
            float4 wr = W4[(j + HD) * (HD / 4) + c4];
            l = fmaf(wl.x, g[c4 * 4 + 0], l);
            l = fmaf(wl.y, g[c4 * 4 + 1], l);
            l = fmaf(wl.z, g[c4 * 4 + 2], l);
            l = fmaf(wl.w, g[c4 * 4 + 3], l);
            r = fmaf(wr.x, g[c4 * 4 + 0], r);
            r = fmaf(wr.y, g[c4 * 4 + 1], r);
            r = fmaf(wr.z, g[c4 * 4 + 2], r);
            r = fmaf(wr.w, g[c4 * 4 + 3], r);
        }
        float val = l * (1.0f / (1.0f + __expf(-r)));
        Hh[(size_t)(b * HD + j) * N3 + v] = __float2half(val);
        if ((unsigned)(v - NSER) < NSER)
            Hmid[(size_t)(b * HD + j) * NSER + (v - NSER)] = val;
    }
}

// depth 1: reads scaled G1T [MJ][NSER], GLU, max with Hmid, transposed write
__global__ __launch_bounds__(128)
void glu2(const float* __restrict__ G, const float* __restrict__ W,
          const float* __restrict__ bias, const float* __restrict__ Hmid,
          float* __restrict__ out)
{
    extern __shared__ float sm2[];           // Ws[8192] + S[128*65]
    float* Ws = sm2;
    float* S  = sm2 + HD2 * HD;
    const int tid = threadIdx.x;
    for (int i = tid; i < HD2 * HD / 4; i += 128)
        ((float4*)Ws)[i] = ((const float4*)W)[i];
    __syncthreads();
    const float4* W4 = (const float4*)Ws;
    const int b = blockIdx.y;
    const int v = blockIdx.x * 128 + tid;
    float g[HD];
    const float* gp = G + (size_t)b * HD * NSER + v;
    #pragma unroll
    for (int c = 0; c < HD; c++) g[c] = gp[(size_t)c * NSER] * INV_ASCALE;
    #pragma unroll 1
    for (int j = 0; j < HD; j++) {
        float l = __ldg(bias + j), r = __ldg(bias + j + HD);
        #pragma unroll
        for (int c4 = 0; c4 < HD / 4; c4++) {
            float4 wl = W4[j * (HD / 4) + c4];
            float4 wr = W4[(j + HD) * (HD / 4) + c4];
            l = fmaf(wl.x, g[c4 * 4 + 0], l);
            l = fmaf(wl.y, g[c4 * 4 + 1], l);
            l = fmaf(wl.z, g[c4 * 4 + 2], l);
            l = fmaf(wl.w, g[c4 * 4 + 3], l);
            r = fmaf(wr.x, g[c4 * 4 + 0], r);
            r = fmaf(wr.y, g[c4 * 4 + 1], r);
            r = fmaf(wr.z, g[c4 * 4 + 2], r);
            r = fmaf(wr.w, g[c4 * 4 + 3], r);
        }
        float val = l * (1.0f / (1.0f + __expf(-r)));
        float m = Hmid[(size_t)(b * HD + j) * NSER + v];
        S[tid * 65 + j] = fmaxf(val, m);
    }
    __syncthreads();
    const int v0 = blockIdx.x * 128;
    for (int i = tid; i < 128 * HD; i += 128) {
        int r = i >> 6, j = i & 63;
        out[(size_t)(v0 + r) * MJ + b * HD + j] = S[r * 65 + j];
    }
}

// ---------------- host -------------------------------------------------------
extern "C" void kernel_launch(void* const* d_in, const int* in_sizes, int n_in,
                              void* d_out, int out_size)
{
    const float* x  = (const float*)d_in[0];
    const float* A  = (const float*)d_in[1];
    const float* W0 = (const float*)d_in[2];
    const float* b0 = (const float*)d_in[3];
    const float* W1 = (const float*)d_in[4];
    const float* b1 = (const float*)d_in[5];
    float* out = (float*)d_out;

    void *XT, *Ah, *Al, *G, *H, *Hmid;
    cudaGetSymbolAddress(&XT, g_XT);
    cudaGetSymbolAddress(&Ah, g_A_hi);   cudaGetSymbolAddress(&Al, g_A_lo);
    cudaGetSymbolAddress(&G,  g_G);      cudaGetSymbolAddress(&H,  g_H);
    cudaGetSymbolAddress(&Hmid, g_Hmid);

    cudaFuncSetAttribute(hmma_gemm, cudaFuncAttributeMaxDynamicSharedMemorySize, SMEM_GEMM);
    cudaFuncSetAttribute(glu2, cudaFuncAttributeMaxDynamicSharedMemorySize,
                         (HD2 * HD + 128 * 65) * (int)sizeof(float));

    // 1) x (3N x 4096 row-major) -> XT (4096 x 3072) fp16
    transpose_h<<<dim3(N3 / 32, MJ / 32), dim3(32, 8)>>>(x, (__half*)XT);
    // 2) A -> fp16 hi/lo, scaled x64 (rows of A are K-major already)
    {
        size_t n = (size_t)N3 * N3;
        split_mat<<<(unsigned)((n + 255) / 256), 256>>>(A,
            (__half*)Ah, (__half*)Al, n);
    }

    // 3) GEMM1: G0T[j,v] = sum_k XT[j,k]*As[v,k]   (4096 x 3072, K=3072)
    hmma_gemm<<<dim3(N3 / BN, MJ / BM), 256, SMEM_GEMM>>>(
        (const __half*)XT, (const __half*)Ah, (const __half*)Al,
        (float*)G, N3, N3);

    // 4) GLU depth 0 (T-space, /64) -> fp16 H + fp32 crop
    glu1<<<dim3(N3 / 128, 64), 128>>>((const float*)G, W0, b0,
        (__half*)H, (float*)Hmid);

    // 5) GEMM2: G1T[j,v'] = sum_w H[j,w]*As[NSER+v',w]   (4096 x 1024)
    hmma_gemm<<<dim3(NSER / BN, MJ / BM), 256, SMEM_GEMM>>>(
        (const __half*)H,
        (const __half*)Ah + (size_t)NSER * N3,
        (const __half*)Al + (size_t)NSER * N3,
        (float*)G, NSER, N3);

    // 6) GLU depth 1 (/64) + max + transposed write to out (N, B, h)
    glu2<<<dim3(NSER / 128, 64), 128,
           (HD2 * HD + 128 * 65) * (int)sizeof(float)>>>(
        (const float*)G, W1, b1, (const float*)Hmid, out);
}